// round 12
// baseline (speedup 1.0000x reference)
#include <cuda_runtime.h>
#include <cstdint>
#include <math.h>

#define C_DIM 256
#define NTOK 2048          // 64 * 32 tokens per side per batch
#define SB_COUNT 16        // side(2) * batch(8)

// ---------------- scratch (static device globals; no allocation) ----------------
__device__ float g_featR[8 * C_DIM * 4096];             // tf32-rounded feat (same layout)
__device__ float g_qT[SB_COUNT * C_DIM * NTOK];         // q transposed [sb][c][n]
__device__ float g_kT[SB_COUNT * C_DIM * NTOK];
__device__ float g_vT[SB_COUNT * C_DIM * NTOK];
__device__ float g_attT[SB_COUNT * C_DIM * NTOK];       // attention ctx, transposed + tf32-rounded
__device__ float g_ctxT[SB_COUNT * C_DIM * NTOK];       // out-proj result, transposed [sb][c][n]
__device__ float g_inwT[C_DIM * 768];                   // in_w^T  (tf32-rounded)
__device__ float g_outwT[C_DIM * C_DIM];                // out_w^T (tf32-rounded)
__device__ float g_projwT[1024 * C_DIM];                // proj_w^T(tf32-rounded)

// ---------------- helpers ----------------
__device__ __forceinline__ uint32_t f2tf(float x) {
    uint32_t u; asm("cvt.rna.tf32.f32 %0, %1;" : "=r"(u) : "f"(x)); return u;
}
__device__ __forceinline__ void mma8(float* c, const uint32_t* a, const uint32_t* b) {
    asm volatile("mma.sync.aligned.m16n8k8.row.col.f32.tf32.tf32.f32 "
        "{%0,%1,%2,%3}, {%4,%5,%6,%7}, {%8,%9}, {%0,%1,%2,%3};"
        : "+f"(c[0]), "+f"(c[1]), "+f"(c[2]), "+f"(c[3])
        : "r"(a[0]), "r"(a[1]), "r"(a[2]), "r"(a[3]), "r"(b[0]), "r"(b[1]));
}
__device__ __forceinline__ uint32_t sptr(const void* p) {
    return (uint32_t)__cvta_generic_to_shared(p);
}
#define CPA4(d, s)  asm volatile("cp.async.ca.shared.global [%0], [%1], 4;"  :: "r"(d), "l"(s))
#define CPA16(d, s) asm volatile("cp.async.cg.shared.global [%0], [%1], 16;" :: "r"(d), "l"(s))
#define CPC()  asm volatile("cp.async.commit_group;")
#define CPW1() asm volatile("cp.async.wait_group 1;")
#define CPW0() asm volatile("cp.async.wait_group 0;")

// ---------------- K0: weight transpose + feat rounding (merged) ----------------
__global__ void prep_inputs(const float* __restrict__ feat,
                            const float* __restrict__ in_w,
                            const float* __restrict__ out_w,
                            const float* __restrict__ proj_w) {
    const int bid = blockIdx.x;
    if (bid < 1024) {
        int i = bid * 256 + threadIdx.x;
        if (i < 768 * 256) { int co = i >> 8;  int c = i & 255;  g_inwT[c * 768 + co]  = __uint_as_float(f2tf(in_w[i])); }
        if (i < 256 * 256) { int co = i >> 8;  int c = i & 255;  g_outwT[c * 256 + co] = __uint_as_float(f2tf(out_w[i])); }
        if (i < 256 * 1024){ int co = i >> 10; int j = i & 1023; g_projwT[j * 256 + co] = __uint_as_float(f2tf(proj_w[i])); }
    } else {
        int i = (bid - 1024) * 256 + threadIdx.x;   // float4 index
        float4 v = ((const float4*)feat)[i];
        v.x = __uint_as_float(f2tf(v.x)); v.y = __uint_as_float(f2tf(v.y));
        v.z = __uint_as_float(f2tf(v.z)); v.w = __uint_as_float(f2tf(v.w));
        ((float4*)g_featR)[i] = v;
    }
}

// ---------------- K1: QKV GEMM (tf32 mma, 3-stage cp.async) ----------------
// BM=128 BN=128 BK=16, 256 thr, warp tile 64x32. Writes q/k/v TRANSPOSED [sb][c][n].
__global__ void __launch_bounds__(256) qkv_gemm(const float* __restrict__ in_b) {
    extern __shared__ uint32_t sm[];
    uint32_t* As = sm;              // 3 stages * 2176 words
    uint32_t* Bs = sm + 3 * 2176;

    const int co0 = blockIdx.x * 128;
    const int m0  = blockIdx.y * 128;
    const int sb  = blockIdx.z;
    const int side = sb >> 3, b = sb & 7;
    const bool is_q = (co0 < 256);
    const float* featRB = g_featR + (size_t)b * (C_DIM * 4096);

    const int t = threadIdx.x;
    const int w = t >> 5, lane = t & 31, quad = lane >> 2, tq = lane & 3;
    const int mw = (w & 1) * 64, nw = (w >> 1) * 32;

    const int mm = t & 127;
    const int m  = m0 + mm;
    const int yq = m >> 5, xq = m & 31;
    const int colg = is_q ? (side ? 32 + xq : xq) : (side ? 31 - xq : 63 - xq);
    const int aoff = yq * 64 + colg;
    const int kb0 = t >> 7;   // fills k = kb0 + 2*i

    const uint32_t abase0 = sptr(As), bbase0 = sptr(Bs);

    auto fill = [&](int s, int kt) {
        const int c0 = kt * 16;
        const uint32_t ab = abase0 + s * 8704;
        const uint32_t bb = bbase0 + s * 8704;
#pragma unroll
        for (int i = 0; i < 8; ++i) {
            int k = kb0 + 2 * i;
            CPA4(ab + (k * 136 + mm) * 4, featRB + (size_t)(c0 + k) * 4096 + aoff);
        }
#pragma unroll
        for (int i = 0; i < 2; ++i) {
            int idx = t + 256 * i;
            int k = idx >> 5, jg = idx & 31;
            CPA16(bb + (k * 136 + jg * 4) * 4, g_inwT + (c0 + k) * 768 + co0 + jg * 4);
        }
    };

    float acc[4][4][4];
#pragma unroll
    for (int i = 0; i < 4; ++i)
#pragma unroll
        for (int j = 0; j < 4; ++j)
#pragma unroll
            for (int p = 0; p < 4; ++p) acc[i][j][p] = 0.0f;

    fill(0, 0); CPC();
    fill(1, 1); CPC();

    for (int kt = 0; kt < 16; ++kt) {
        CPW1();
        __syncthreads();
        if (kt + 2 < 16) fill((kt + 2) % 3, kt + 2);
        CPC();
        const uint32_t* A = As + (kt % 3) * 2176;
        const uint32_t* B = Bs + (kt % 3) * 2176;
#pragma unroll
        for (int kb = 0; kb < 2; ++kb) {
            const int k0 = kb * 8;
            uint32_t af[4][4], bf[4][2];
#pragma unroll
            for (int i = 0; i < 4; ++i) {
                af[i][0] = A[(k0 + tq) * 136 + mw + i * 16 + quad];
                af[i][1] = A[(k0 + tq) * 136 + mw + i * 16 + quad + 8];
                af[i][2] = A[(k0 + tq + 4) * 136 + mw + i * 16 + quad];
                af[i][3] = A[(k0 + tq + 4) * 136 + mw + i * 16 + quad + 8];
            }
#pragma unroll
            for (int j = 0; j < 4; ++j) {
                bf[j][0] = B[(k0 + tq) * 136 + nw + j * 8 + quad];
                bf[j][1] = B[(k0 + tq + 4) * 136 + nw + j * 8 + quad];
            }
#pragma unroll
            for (int i = 0; i < 4; ++i)
#pragma unroll
                for (int j = 0; j < 4; ++j)
                    mma8(acc[i][j], af[i], bf[j]);
        }
    }

    // transposed epilogue: dst[cl][row]
#pragma unroll
    for (int i = 0; i < 4; ++i) {
        int r0 = m0 + mw + i * 16 + quad;
#pragma unroll
        for (int j = 0; j < 4; ++j) {
            int co = co0 + nw + j * 8 + tq * 2;
            float b0 = in_b[co], b1 = in_b[co + 1];
            float* dst = (co < 256) ? g_qT : ((co < 512) ? g_kT : g_vT);
            int cl = co & 255;
            float* base0 = dst + ((size_t)sb * C_DIM + cl) * NTOK;
            float* base1 = base0 + NTOK;
            base0[r0]     = acc[i][j][0] + b0;
            base1[r0]     = acc[i][j][1] + b1;
            base0[r0 + 8] = acc[i][j][2] + b0;
            base1[r0 + 8] = acc[i][j][3] + b1;
        }
    }
}

// ---------------- K2: sparse attention v2 (thread-per-token, smem tiles) ----------------
__global__ void __launch_bounds__(128, 4) attn_kernel() {
    __shared__ float smk[2][16 * 264];

    const int t = threadIdx.x;
    const int yblk = blockIdx.x;     // 0..15 (4 rows each)
    const int hd   = blockIdx.y;     // 0..3
    const int sb   = blockIdx.z;     // 0..15
    const int n0 = yblk * 128;
    const int n  = n0 + t;
    const int y = n >> 5, x = n & 31;
    const int lt = 64 + t;           // local token index within tile (tile starts at n0-64)

    const float* qTB = g_qT + ((size_t)sb * C_DIM + hd * 64) * NTOK;
    const float* kTB = g_kT + ((size_t)sb * C_DIM + hd * 64) * NTOK;
    const float* vTB = g_vT + ((size_t)sb * C_DIM + hd * 64) * NTOK;

    // zero pad columns (cols [0,4) and [260,264) of each of 16 rows, both buffers)
    for (int i = t; i < 256; i += 128) {
        int buf = i >> 7, rem = i & 127;
        int row = rem >> 3, c8 = rem & 7;
        int col = (c8 < 4) ? c8 : (256 + c8);
        smk[buf][row * 264 + col] = 0.0f;
    }

    const int ody[13] = {0, 0, 0, 0, 0, -1, -1, -1, 1, 1, 1, -2, 2};
    const int odx[13] = {0,-1, 1,-2, 2,  0, -1,  1, 0,-1, 1,  0, 0};

    bool va[13];
#pragma unroll
    for (int i = 0; i < 13; ++i) {
        int yy = y + ody[i], xx = x + odx[i];
        va[i] = (yy >= 0) && (yy < 64) && (xx >= 0) && (xx < 32);
    }

    // q in registers (reused 13x per channel; later reused as output accumulator)
    float qa[64];
#pragma unroll
    for (int d = 0; d < 64; ++d) qa[d] = qTB[(size_t)d * NTOK + n];

    const int y0m2 = (n0 >> 5) - 2;
    auto fill = [&](int buf, int c) {
        const float* src = (c < 4) ? (kTB + (size_t)(c * 16) * NTOK)
                                   : (vTB + (size_t)((c - 4) * 16) * NTOK);
        uint32_t dst = sptr(&smk[buf][0]);
#pragma unroll
        for (int i = 0; i < 8; ++i) {
            int idx = t + 128 * i;
            int d = idx >> 6, jj = idx & 63;
            int yy = y0m2 + (jj >> 3);
            int yc = min(max(yy, 0), 63);
            int sn = yc * 32 + (jj & 7) * 4;
            CPA16(dst + (d * 264 + 4 + jj * 4) * 4, src + (size_t)d * NTOK + sn);
        }
    };

    float sc[13];
#pragma unroll
    for (int i = 0; i < 13; ++i) sc[i] = 0.0f;

    fill(0, 0); CPC();

#pragma unroll
    for (int c = 0; c < 8; ++c) {
        if (c < 7) { fill((c + 1) & 1, c + 1); CPC(); CPW1(); }
        else       { CPW0(); }
        __syncthreads();
        const float* buf = smk[c & 1];
        if (c < 4) {
#pragma unroll
            for (int dd = 0; dd < 16; ++dd) {
                float qv = qa[c * 16 + dd];
                const float* base = buf + dd * 264 + 4 + lt;
#pragma unroll
                for (int i = 0; i < 13; ++i)
                    sc[i] += qv * base[ody[i] * 32 + odx[i]];
            }
            if (c == 3) {
                float mx = -1e30f;
#pragma unroll
                for (int i = 0; i < 13; ++i) {
                    sc[i] = va[i] ? sc[i] * 0.125f : -1e30f;
                    mx = fmaxf(mx, sc[i]);
                }
                float ssum = 0.0f;
#pragma unroll
                for (int i = 0; i < 13; ++i) {
                    sc[i] = va[i] ? __expf(sc[i] - mx) : 0.0f;
                    ssum += sc[i];
                }
                float inv = 1.0f / ssum;
#pragma unroll
                for (int i = 0; i < 13; ++i) sc[i] *= inv;
            }
        } else {
#pragma unroll
            for (int dd = 0; dd < 16; ++dd) {
                const float* base = buf + dd * 264 + 4 + lt;
                float a = 0.0f;
#pragma unroll
                for (int i = 0; i < 13; ++i)
                    a += sc[i] * base[ody[i] * 32 + odx[i]];
                qa[(c - 4) * 16 + dd] = a;
            }
        }
        __syncthreads();
    }

    // store transposed + tf32-rounded, coalesced over n
    float* oB = g_attT + ((size_t)sb * C_DIM + hd * 64) * NTOK + n;
#pragma unroll
    for (int d = 0; d < 64; ++d)
        oB[(size_t)d * NTOK] = __uint_as_float(f2tf(qa[d]));
}

// ---------------- K3: out-proj GEMM (tf32 mma, 3-stage cp.async), writes g_ctxT ----------------
__global__ void __launch_bounds__(256) outproj_gemm(const float* __restrict__ out_b) {
    extern __shared__ uint32_t sm[];
    uint32_t* As = sm;
    uint32_t* Bs = sm + 3 * 2176;

    const int co0 = blockIdx.x * 128;
    const int m0  = blockIdx.y * 128;
    const int sb  = blockIdx.z;
    const float* attTB = g_attT + (size_t)sb * C_DIM * NTOK;

    const int t = threadIdx.x;
    const int w = t >> 5, lane = t & 31, quad = lane >> 2, tq = lane & 3;
    const int mw = (w & 1) * 64, nw = (w >> 1) * 32;

    const uint32_t abase0 = sptr(As), bbase0 = sptr(Bs);

    auto fill = [&](int s, int kt) {
        const int c0 = kt * 16;
        const uint32_t ab = abase0 + s * 8704;
        const uint32_t bb = bbase0 + s * 8704;
#pragma unroll
        for (int i = 0; i < 2; ++i) {
            int idx = t + 256 * i;
            int k = idx >> 5, mg = idx & 31;
            CPA16(ab + (k * 136 + mg * 4) * 4, attTB + (size_t)(c0 + k) * NTOK + m0 + mg * 4);
            CPA16(bb + (k * 136 + mg * 4) * 4, g_outwT + (c0 + k) * 256 + co0 + mg * 4);
        }
    };

    float acc[4][4][4];
#pragma unroll
    for (int i = 0; i < 4; ++i)
#pragma unroll
        for (int j = 0; j < 4; ++j)
#pragma unroll
            for (int p = 0; p < 4; ++p) acc[i][j][p] = 0.0f;

    fill(0, 0); CPC();
    fill(1, 1); CPC();

    for (int kt = 0; kt < 16; ++kt) {
        CPW1();
        __syncthreads();
        if (kt + 2 < 16) fill((kt + 2) % 3, kt + 2);
        CPC();
        const uint32_t* A = As + (kt % 3) * 2176;
        const uint32_t* B = Bs + (kt % 3) * 2176;
#pragma unroll
        for (int kb = 0; kb < 2; ++kb) {
            const int k0 = kb * 8;
            uint32_t af[4][4], bf[4][2];
#pragma unroll
            for (int i = 0; i < 4; ++i) {
                af[i][0] = A[(k0 + tq) * 136 + mw + i * 16 + quad];
                af[i][1] = A[(k0 + tq) * 136 + mw + i * 16 + quad + 8];
                af[i][2] = A[(k0 + tq + 4) * 136 + mw + i * 16 + quad];
                af[i][3] = A[(k0 + tq + 4) * 136 + mw + i * 16 + quad + 8];
            }
#pragma unroll
            for (int j = 0; j < 4; ++j) {
                bf[j][0] = B[(k0 + tq) * 136 + nw + j * 8 + quad];
                bf[j][1] = B[(k0 + tq + 4) * 136 + nw + j * 8 + quad];
            }
#pragma unroll
            for (int i = 0; i < 4; ++i)
#pragma unroll
                for (int j = 0; j < 4; ++j)
                    mma8(acc[i][j], af[i], bf[j]);
        }
    }

#pragma unroll
    for (int i = 0; i < 4; ++i) {
        int r0 = m0 + mw + i * 16 + quad;
#pragma unroll
        for (int j = 0; j < 4; ++j) {
            int co = co0 + nw + j * 8 + tq * 2;
            float b0 = out_b[co], b1 = out_b[co + 1];
            float* base = g_ctxT + (size_t)sb * C_DIM * NTOK;
            base[(size_t)co * NTOK + r0]           = acc[i][j][0] + b0;
            base[(size_t)(co + 1) * NTOK + r0]     = acc[i][j][1] + b1;
            base[(size_t)co * NTOK + r0 + 8]       = acc[i][j][2] + b0;
            base[(size_t)(co + 1) * NTOK + r0 + 8] = acc[i][j][3] + b1;
        }
    }
}

// ---------------- K4: fused asym + proj + LN + ReLU (chunk-major K order) ----------------
// K permutation: iter kt -> part=(kt&3), chunk=(kt>>2); B row block j0 = part*256 + chunk*16.
// rq/rc loaded once per chunk (every 4th iter), reused for all 4 parts.
__global__ void __launch_bounds__(512) fused_proj_ln(const float* __restrict__ proj_b,
                                                     const float* __restrict__ ln_g,
                                                     const float* __restrict__ ln_b,
                                                     float* __restrict__ out) {
    extern __shared__ uint32_t sm[];
    uint32_t* As = sm;                       // 2 * 2176
    uint32_t* Bs = sm + 2 * 2176;            // 3 * 4224
    float2*  red = (float2*)(sm + 2 * 2176 + 3 * 4224);   // [128][4]

    const int m0 = blockIdx.y * 128;
    const int sb = blockIdx.z;
    const int side = sb >> 3, b = sb & 7;
    const float* featRB = g_featR + (size_t)b * (C_DIM * 4096);
    const float* ctxTB  = g_ctxT + (size_t)sb * C_DIM * NTOK;

    const int t = threadIdx.x;
    const int w = t >> 5, lane = t & 31, quad = lane >> 2, tq = lane & 3;
    const int wm = w & 3, nwi = w >> 2;
    const int mw = wm * 32, nwcol = nwi * 64;

    const int amm = t & 127, akb = t >> 7;   // fills k-local = akb + 4*i, i<4
    const int lm = m0 + amm;
    const int ly = lm >> 5, lx = lm & 31;
    const int qoff = ly * 64 + (side ? 32 + lx : lx);

    const uint32_t bbase0 = sptr(Bs);

    auto fillB = [&](int s, int kt) {
        const int j0 = ((kt & 3) << 8) + ((kt >> 2) << 4);   // permuted B row block
        const uint32_t bb = bbase0 + s * 16896;
#pragma unroll
        for (int i = 0; i < 2; ++i) {
            int idx = t + 512 * i;
            int k = idx >> 6, jg = idx & 63;
            CPA16(bb + (k * 264 + jg * 4) * 4, g_projwT + (j0 + k) * 256 + jg * 4);
        }
    };

    float acc[2][8][4];
#pragma unroll
    for (int i = 0; i < 2; ++i)
#pragma unroll
        for (int j = 0; j < 8; ++j)
#pragma unroll
            for (int p = 0; p < 4; ++p) acc[i][j][p] = 0.0f;

    fillB(0, 0); CPC();
    fillB(1, 1); CPC();

    // load chunk 0 (channels akb+4i of chunk 0) and store part 0 into stage 0
    float rq[4], rc[4];
#pragma unroll
    for (int i = 0; i < 4; ++i) {
        int jc = akb + 4 * i;                // chunk 0 channel
        rq[i] = featRB[(size_t)jc * 4096 + qoff];
        rc[i] = ctxTB[(size_t)jc * NTOK + lm];
        As[jc * 136 + amm] = __float_as_uint(rq[i]);   // featR pre-rounded
    }

    for (int kt = 0; kt < 64; ++kt) {
        CPW1();
        __syncthreads();
        if (kt + 2 < 64) fillB((kt + 2) % 3, kt + 2);
        CPC();

        // new chunk's rq/rc needed for STS at end of this iter?
        const bool newchunk = (((kt + 1) & 3) == 0) && (kt < 63);
        if (newchunk) {
            const int cc = (kt + 1) >> 2;
#pragma unroll
            for (int i = 0; i < 4; ++i) {
                int jc = cc * 16 + akb + 4 * i;
                rq[i] = featRB[(size_t)jc * 4096 + qoff];
                rc[i] = ctxTB[(size_t)jc * NTOK + lm];
            }
        }

        // compute stage kt
        const uint32_t* A = As + (kt & 1) * 2176;
        const uint32_t* B = Bs + (kt % 3) * 4224;
#pragma unroll
        for (int kb = 0; kb < 2; ++kb) {
            const int k0 = kb * 8;
            uint32_t af[2][4], bf[8][2];
#pragma unroll
            for (int i = 0; i < 2; ++i) {
                af[i][0] = A[(k0 + tq) * 136 + mw + i * 16 + quad];
                af[i][1] = A[(k0 + tq) * 136 + mw + i * 16 + quad + 8];
                af[i][2] = A[(k0 + tq + 4) * 136 + mw + i * 16 + quad];
                af[i][3] = A[(k0 + tq + 4) * 136 + mw + i * 16 + quad + 8];
            }
#pragma unroll
            for (int j = 0; j < 8; ++j) {
                bf[j][0] = B[(k0 + tq) * 264 + nwcol + j * 8 + quad];
                bf[j][1] = B[(k0 + tq + 4) * 264 + nwcol + j * 8 + quad];
            }
#pragma unroll
            for (int i = 0; i < 2; ++i)
#pragma unroll
                for (int j = 0; j < 8; ++j)
                    mma8(acc[i][j], af[i], bf[j]);
        }

        // STS A(kt+1): part = (kt+1)&3 on current rq/rc
        if (kt < 63) {
            const int np = (kt + 1) & 3;
            uint32_t* An = As + ((kt + 1) & 1) * 2176;
#pragma unroll
            for (int i = 0; i < 4; ++i) {
                float v;
                if (np == 0)      v = rq[i];
                else if (np == 1) v = rc[i];
                else if (np == 2) v = fabsf(rq[i] - rc[i]);
                else              v = rq[i] * rc[i];
                An[(akb + 4 * i) * 136 + amm] = f2tf(v);
            }
        }
    }

    // ---- epilogue: +bias, LN(256), relu, transposed scatter ----
#pragma unroll
    for (int j = 0; j < 8; ++j) {
        int co = nwcol + j * 8 + tq * 2;
        float2 pb = *(const float2*)&proj_b[co];
#pragma unroll
        for (int i = 0; i < 2; ++i) {
            acc[i][j][0] += pb.x; acc[i][j][1] += pb.y;
            acc[i][j][2] += pb.x; acc[i][j][3] += pb.y;
        }
    }

    __syncthreads();
#pragma unroll
    for (int i = 0; i < 2; ++i)
#pragma unroll
        for (int u = 0; u < 2; ++u) {
            float s1 = 0.0f, s2 = 0.0f;
#pragma unroll
            for (int j = 0; j < 8; ++j) {
                float x0 = acc[i][j][2 * u], x1 = acc[i][j][2 * u + 1];
                s1 += x0 + x1; s2 += x0 * x0 + x1 * x1;
            }
            s1 += __shfl_xor_sync(0xffffffffu, s1, 1);
            s2 += __shfl_xor_sync(0xffffffffu, s2, 1);
            s1 += __shfl_xor_sync(0xffffffffu, s1, 2);
            s2 += __shfl_xor_sync(0xffffffffu, s2, 2);
            if (tq == 0) {
                int r = mw + i * 16 + u * 8 + quad;
                red[r * 4 + nwi] = make_float2(s1, s2);
            }
        }
    __syncthreads();

#pragma unroll
    for (int i = 0; i < 2; ++i)
#pragma unroll
        for (int u = 0; u < 2; ++u) {
            int r = mw + i * 16 + u * 8 + quad;
            float s1 = 0.0f, s2 = 0.0f;
#pragma unroll
            for (int p = 0; p < 4; ++p) { float2 v = red[r * 4 + p]; s1 += v.x; s2 += v.y; }
            float mu   = s1 * (1.0f / 256.0f);
            float var  = s2 * (1.0f / 256.0f) - mu * mu;
            float rstd = rsqrtf(var + 1e-5f);

            int grow = m0 + r;
            int y = grow >> 5, x = grow & 31;
            int xg = side ? (32 + x) : x;
            size_t obase = (size_t)b * C_DIM * 4096 + y * 64 + xg;
#pragma unroll
            for (int j = 0; j < 8; ++j) {
                int co = nwcol + j * 8 + tq * 2;
                float g0 = ln_g[co], g1 = ln_g[co + 1];
                float l0 = ln_b[co], l1 = ln_b[co + 1];
                float v0 = fmaxf((acc[i][j][2 * u]     - mu) * rstd * g0 + l0, 0.0f);
                float v1 = fmaxf((acc[i][j][2 * u + 1] - mu) * rstd * g1 + l1, 0.0f);
                out[obase + (size_t)co * 4096]       = v0;
                out[obase + (size_t)(co + 1) * 4096] = v1;
            }
        }
}

// ---------------- launch ----------------
extern "C" void kernel_launch(void* const* d_in, const int* in_sizes, int n_in,
                              void* d_out, int out_size) {
    const float* feat   = (const float*)d_in[0];
    const float* in_w   = (const float*)d_in[1];
    const float* in_b   = (const float*)d_in[2];
    const float* out_w  = (const float*)d_in[3];
    const float* out_b  = (const float*)d_in[4];
    const float* proj_w = (const float*)d_in[5];
    const float* proj_b = (const float*)d_in[6];
    const float* ln_g   = (const float*)d_in[7];
    const float* ln_b   = (const float*)d_in[8];
    float* out = (float*)d_out;

    const int QKV_SMEM = 3 * 2176 * 2 * 4;                         // 52224 B
    const int K4_SMEM  = (2 * 2176 + 3 * 4224) * 4 + 128 * 4 * 8;  // 72192 B
    cudaFuncSetAttribute(qkv_gemm,      cudaFuncAttributeMaxDynamicSharedMemorySize, QKV_SMEM);
    cudaFuncSetAttribute(outproj_gemm,  cudaFuncAttributeMaxDynamicSharedMemorySize, QKV_SMEM);
    cudaFuncSetAttribute(fused_proj_ln, cudaFuncAttributeMaxDynamicSharedMemorySize, K4_SMEM);

    prep_inputs<<<9216, 256>>>(feat, in_w, out_w, proj_w);
    qkv_gemm<<<dim3(6, 16, 16), 256, QKV_SMEM>>>(in_b);
    attn_kernel<<<dim3(16, 4, 16), 128>>>();
    outproj_gemm<<<dim3(2, 16, 16), 256, QKV_SMEM>>>(out_b);
    fused_proj_ln<<<dim3(1, 16, 16), 512, K4_SMEM>>>(proj_b, ln_g, ln_b, out);
}

// round 14
// speedup vs baseline: 1.4626x; 1.4626x over previous
#include <cuda_runtime.h>
#include <cstdint>
#include <math.h>

#define C_DIM 256
#define NTOK 2048          // 64 * 32 tokens per side per batch
#define SB_COUNT 16        // side(2) * batch(8)

// ---------------- scratch (static device globals; no allocation) ----------------
__device__ float g_featR[8 * C_DIM * 4096];             // tf32-rounded feat (same layout)
__device__ float g_qT[SB_COUNT * C_DIM * NTOK];         // q transposed [sb][c][n]
__device__ float g_kT[SB_COUNT * C_DIM * NTOK];
__device__ float g_vT[SB_COUNT * C_DIM * NTOK];
__device__ float g_attT[SB_COUNT * C_DIM * NTOK];       // attention ctx, transposed + tf32-rounded
__device__ float g_ctxT[SB_COUNT * C_DIM * NTOK];       // out-proj result, transposed [sb][c][n]
__device__ float g_inwT[C_DIM * 768];                   // in_w^T  (tf32-rounded)
__device__ float g_outwT[C_DIM * C_DIM];                // out_w^T (tf32-rounded)
__device__ float g_projwT[1024 * C_DIM];                // proj_w^T(tf32-rounded)

// ---------------- helpers ----------------
__device__ __forceinline__ uint32_t f2tf(float x) {
    uint32_t u; asm("cvt.rna.tf32.f32 %0, %1;" : "=r"(u) : "f"(x)); return u;
}
__device__ __forceinline__ void mma8(float* c, const uint32_t* a, const uint32_t* b) {
    asm volatile("mma.sync.aligned.m16n8k8.row.col.f32.tf32.tf32.f32 "
        "{%0,%1,%2,%3}, {%4,%5,%6,%7}, {%8,%9}, {%0,%1,%2,%3};"
        : "+f"(c[0]), "+f"(c[1]), "+f"(c[2]), "+f"(c[3])
        : "r"(a[0]), "r"(a[1]), "r"(a[2]), "r"(a[3]), "r"(b[0]), "r"(b[1]));
}
__device__ __forceinline__ uint32_t sptr(const void* p) {
    return (uint32_t)__cvta_generic_to_shared(p);
}
#define CPA4(d, s)  asm volatile("cp.async.ca.shared.global [%0], [%1], 4;"  :: "r"(d), "l"(s))
#define CPA16(d, s) asm volatile("cp.async.cg.shared.global [%0], [%1], 16;" :: "r"(d), "l"(s))
#define CPC()  asm volatile("cp.async.commit_group;")
#define CPW1() asm volatile("cp.async.wait_group 1;")
#define CPW0() asm volatile("cp.async.wait_group 0;")

// ---------------- K0: weight transpose + feat rounding (merged) ----------------
__global__ void prep_inputs(const float* __restrict__ feat,
                            const float* __restrict__ in_w,
                            const float* __restrict__ out_w,
                            const float* __restrict__ proj_w) {
    const int bid = blockIdx.x;
    if (bid < 1024) {
        int i = bid * 256 + threadIdx.x;
        if (i < 768 * 256) { int co = i >> 8;  int c = i & 255;  g_inwT[c * 768 + co]  = __uint_as_float(f2tf(in_w[i])); }
        if (i < 256 * 256) { int co = i >> 8;  int c = i & 255;  g_outwT[c * 256 + co] = __uint_as_float(f2tf(out_w[i])); }
        if (i < 256 * 1024){ int co = i >> 10; int j = i & 1023; g_projwT[j * 256 + co] = __uint_as_float(f2tf(proj_w[i])); }
    } else {
        int i = (bid - 1024) * 256 + threadIdx.x;   // float4 index
        float4 v = ((const float4*)feat)[i];
        v.x = __uint_as_float(f2tf(v.x)); v.y = __uint_as_float(f2tf(v.y));
        v.z = __uint_as_float(f2tf(v.z)); v.w = __uint_as_float(f2tf(v.w));
        ((float4*)g_featR)[i] = v;
    }
}

// ---------------- K1: QKV GEMM (tf32 mma, 3-stage cp.async) ----------------
// BM=128 BN=128 BK=16, 256 thr, warp tile 64x32. Writes q/k/v TRANSPOSED [sb][c][n].
__global__ void __launch_bounds__(256) qkv_gemm(const float* __restrict__ in_b) {
    extern __shared__ uint32_t sm[];
    uint32_t* As = sm;              // 3 stages * 2176 words
    uint32_t* Bs = sm + 3 * 2176;

    const int co0 = blockIdx.x * 128;
    const int m0  = blockIdx.y * 128;
    const int sb  = blockIdx.z;
    const int side = sb >> 3, b = sb & 7;
    const bool is_q = (co0 < 256);
    const float* featRB = g_featR + (size_t)b * (C_DIM * 4096);

    const int t = threadIdx.x;
    const int w = t >> 5, lane = t & 31, quad = lane >> 2, tq = lane & 3;
    const int mw = (w & 1) * 64, nw = (w >> 1) * 32;

    const int mm = t & 127;
    const int m  = m0 + mm;
    const int yq = m >> 5, xq = m & 31;
    const int colg = is_q ? (side ? 32 + xq : xq) : (side ? 31 - xq : 63 - xq);
    const int aoff = yq * 64 + colg;
    const int kb0 = t >> 7;   // fills k = kb0 + 2*i

    const uint32_t abase0 = sptr(As), bbase0 = sptr(Bs);

    auto fill = [&](int s, int kt) {
        const int c0 = kt * 16;
        const uint32_t ab = abase0 + s * 8704;
        const uint32_t bb = bbase0 + s * 8704;
#pragma unroll
        for (int i = 0; i < 8; ++i) {
            int k = kb0 + 2 * i;
            CPA4(ab + (k * 136 + mm) * 4, featRB + (size_t)(c0 + k) * 4096 + aoff);
        }
#pragma unroll
        for (int i = 0; i < 2; ++i) {
            int idx = t + 256 * i;
            int k = idx >> 5, jg = idx & 31;
            CPA16(bb + (k * 136 + jg * 4) * 4, g_inwT + (c0 + k) * 768 + co0 + jg * 4);
        }
    };

    float acc[4][4][4];
#pragma unroll
    for (int i = 0; i < 4; ++i)
#pragma unroll
        for (int j = 0; j < 4; ++j)
#pragma unroll
            for (int p = 0; p < 4; ++p) acc[i][j][p] = 0.0f;

    fill(0, 0); CPC();
    fill(1, 1); CPC();

    for (int kt = 0; kt < 16; ++kt) {
        CPW1();
        __syncthreads();
        if (kt + 2 < 16) fill((kt + 2) % 3, kt + 2);
        CPC();
        const uint32_t* A = As + (kt % 3) * 2176;
        const uint32_t* B = Bs + (kt % 3) * 2176;
#pragma unroll
        for (int kb = 0; kb < 2; ++kb) {
            const int k0 = kb * 8;
            uint32_t af[4][4], bf[4][2];
#pragma unroll
            for (int i = 0; i < 4; ++i) {
                af[i][0] = A[(k0 + tq) * 136 + mw + i * 16 + quad];
                af[i][1] = A[(k0 + tq) * 136 + mw + i * 16 + quad + 8];
                af[i][2] = A[(k0 + tq + 4) * 136 + mw + i * 16 + quad];
                af[i][3] = A[(k0 + tq + 4) * 136 + mw + i * 16 + quad + 8];
            }
#pragma unroll
            for (int j = 0; j < 4; ++j) {
                bf[j][0] = B[(k0 + tq) * 136 + nw + j * 8 + quad];
                bf[j][1] = B[(k0 + tq + 4) * 136 + nw + j * 8 + quad];
            }
#pragma unroll
            for (int i = 0; i < 4; ++i)
#pragma unroll
                for (int j = 0; j < 4; ++j)
                    mma8(acc[i][j], af[i], bf[j]);
        }
    }

    // transposed epilogue: dst[cl][row]
#pragma unroll
    for (int i = 0; i < 4; ++i) {
        int r0 = m0 + mw + i * 16 + quad;
#pragma unroll
        for (int j = 0; j < 4; ++j) {
            int co = co0 + nw + j * 8 + tq * 2;
            float b0 = in_b[co], b1 = in_b[co + 1];
            float* dst = (co < 256) ? g_qT : ((co < 512) ? g_kT : g_vT);
            int cl = co & 255;
            float* base0 = dst + ((size_t)sb * C_DIM + cl) * NTOK;
            float* base1 = base0 + NTOK;
            base0[r0]     = acc[i][j][0] + b0;
            base1[r0]     = acc[i][j][1] + b1;
            base0[r0 + 8] = acc[i][j][2] + b0;
            base1[r0 + 8] = acc[i][j][3] + b1;
        }
    }
}

// ---------------- K2: sparse attention v2 (thread-per-token, smem tiles) ----------------
__global__ void __launch_bounds__(128, 4) attn_kernel() {
    __shared__ float smk[2][16 * 264];

    const int t = threadIdx.x;
    const int yblk = blockIdx.x;     // 0..15 (4 rows each)
    const int hd   = blockIdx.y;     // 0..3
    const int sb   = blockIdx.z;     // 0..15
    const int n0 = yblk * 128;
    const int n  = n0 + t;
    const int y = n >> 5, x = n & 31;
    const int lt = 64 + t;           // local token index within tile (tile starts at n0-64)

    const float* qTB = g_qT + ((size_t)sb * C_DIM + hd * 64) * NTOK;
    const float* kTB = g_kT + ((size_t)sb * C_DIM + hd * 64) * NTOK;
    const float* vTB = g_vT + ((size_t)sb * C_DIM + hd * 64) * NTOK;

    // zero pad columns (cols [0,4) and [260,264) of each of 16 rows, both buffers)
    for (int i = t; i < 256; i += 128) {
        int buf = i >> 7, rem = i & 127;
        int row = rem >> 3, c8 = rem & 7;
        int col = (c8 < 4) ? c8 : (256 + c8);
        smk[buf][row * 264 + col] = 0.0f;
    }

    const int ody[13] = {0, 0, 0, 0, 0, -1, -1, -1, 1, 1, 1, -2, 2};
    const int odx[13] = {0,-1, 1,-2, 2,  0, -1,  1, 0,-1, 1,  0, 0};

    bool va[13];
#pragma unroll
    for (int i = 0; i < 13; ++i) {
        int yy = y + ody[i], xx = x + odx[i];
        va[i] = (yy >= 0) && (yy < 64) && (xx >= 0) && (xx < 32);
    }

    // q in registers (reused 13x per channel; later reused as output accumulator)
    float qa[64];
#pragma unroll
    for (int d = 0; d < 64; ++d) qa[d] = qTB[(size_t)d * NTOK + n];

    const int y0m2 = (n0 >> 5) - 2;
    auto fill = [&](int buf, int c) {
        const float* src = (c < 4) ? (kTB + (size_t)(c * 16) * NTOK)
                                   : (vTB + (size_t)((c - 4) * 16) * NTOK);
        uint32_t dst = sptr(&smk[buf][0]);
#pragma unroll
        for (int i = 0; i < 8; ++i) {
            int idx = t + 128 * i;
            int d = idx >> 6, jj = idx & 63;
            int yy = y0m2 + (jj >> 3);
            int yc = min(max(yy, 0), 63);
            int sn = yc * 32 + (jj & 7) * 4;
            CPA16(dst + (d * 264 + 4 + jj * 4) * 4, src + (size_t)d * NTOK + sn);
        }
    };

    float sc[13];
#pragma unroll
    for (int i = 0; i < 13; ++i) sc[i] = 0.0f;

    fill(0, 0); CPC();

#pragma unroll
    for (int c = 0; c < 8; ++c) {
        if (c < 7) { fill((c + 1) & 1, c + 1); CPC(); CPW1(); }
        else       { CPW0(); }
        __syncthreads();
        const float* buf = smk[c & 1];
        if (c < 4) {
#pragma unroll
            for (int dd = 0; dd < 16; ++dd) {
                float qv = qa[c * 16 + dd];
                const float* base = buf + dd * 264 + 4 + lt;
#pragma unroll
                for (int i = 0; i < 13; ++i)
                    sc[i] += qv * base[ody[i] * 32 + odx[i]];
            }
            if (c == 3) {
                float mx = -1e30f;
#pragma unroll
                for (int i = 0; i < 13; ++i) {
                    sc[i] = va[i] ? sc[i] * 0.125f : -1e30f;
                    mx = fmaxf(mx, sc[i]);
                }
                float ssum = 0.0f;
#pragma unroll
                for (int i = 0; i < 13; ++i) {
                    sc[i] = va[i] ? __expf(sc[i] - mx) : 0.0f;
                    ssum += sc[i];
                }
                float inv = 1.0f / ssum;
#pragma unroll
                for (int i = 0; i < 13; ++i) sc[i] *= inv;
            }
        } else {
#pragma unroll
            for (int dd = 0; dd < 16; ++dd) {
                const float* base = buf + dd * 264 + 4 + lt;
                float a = 0.0f;
#pragma unroll
                for (int i = 0; i < 13; ++i)
                    a += sc[i] * base[ody[i] * 32 + odx[i]];
                qa[(c - 4) * 16 + dd] = a;
            }
        }
        __syncthreads();
    }

    // store transposed + tf32-rounded, coalesced over n
    float* oB = g_attT + ((size_t)sb * C_DIM + hd * 64) * NTOK + n;
#pragma unroll
    for (int d = 0; d < 64; ++d)
        oB[(size_t)d * NTOK] = __uint_as_float(f2tf(qa[d]));
}

// ---------------- K3: out-proj GEMM (tf32 mma, 3-stage cp.async), writes g_ctxT ----------------
__global__ void __launch_bounds__(256) outproj_gemm(const float* __restrict__ out_b) {
    extern __shared__ uint32_t sm[];
    uint32_t* As = sm;
    uint32_t* Bs = sm + 3 * 2176;

    const int co0 = blockIdx.x * 128;
    const int m0  = blockIdx.y * 128;
    const int sb  = blockIdx.z;
    const float* attTB = g_attT + (size_t)sb * C_DIM * NTOK;

    const int t = threadIdx.x;
    const int w = t >> 5, lane = t & 31, quad = lane >> 2, tq = lane & 3;
    const int mw = (w & 1) * 64, nw = (w >> 1) * 32;

    const uint32_t abase0 = sptr(As), bbase0 = sptr(Bs);

    auto fill = [&](int s, int kt) {
        const int c0 = kt * 16;
        const uint32_t ab = abase0 + s * 8704;
        const uint32_t bb = bbase0 + s * 8704;
#pragma unroll
        for (int i = 0; i < 2; ++i) {
            int idx = t + 256 * i;
            int k = idx >> 5, mg = idx & 31;
            CPA16(ab + (k * 136 + mg * 4) * 4, attTB + (size_t)(c0 + k) * NTOK + m0 + mg * 4);
            CPA16(bb + (k * 136 + mg * 4) * 4, g_outwT + (c0 + k) * 256 + co0 + mg * 4);
        }
    };

    float acc[4][4][4];
#pragma unroll
    for (int i = 0; i < 4; ++i)
#pragma unroll
        for (int j = 0; j < 4; ++j)
#pragma unroll
            for (int p = 0; p < 4; ++p) acc[i][j][p] = 0.0f;

    fill(0, 0); CPC();
    fill(1, 1); CPC();

    for (int kt = 0; kt < 16; ++kt) {
        CPW1();
        __syncthreads();
        if (kt + 2 < 16) fill((kt + 2) % 3, kt + 2);
        CPC();
        const uint32_t* A = As + (kt % 3) * 2176;
        const uint32_t* B = Bs + (kt % 3) * 2176;
#pragma unroll
        for (int kb = 0; kb < 2; ++kb) {
            const int k0 = kb * 8;
            uint32_t af[4][4], bf[4][2];
#pragma unroll
            for (int i = 0; i < 4; ++i) {
                af[i][0] = A[(k0 + tq) * 136 + mw + i * 16 + quad];
                af[i][1] = A[(k0 + tq) * 136 + mw + i * 16 + quad + 8];
                af[i][2] = A[(k0 + tq + 4) * 136 + mw + i * 16 + quad];
                af[i][3] = A[(k0 + tq + 4) * 136 + mw + i * 16 + quad + 8];
            }
#pragma unroll
            for (int j = 0; j < 4; ++j) {
                bf[j][0] = B[(k0 + tq) * 136 + nw + j * 8 + quad];
                bf[j][1] = B[(k0 + tq + 4) * 136 + nw + j * 8 + quad];
            }
#pragma unroll
            for (int i = 0; i < 4; ++i)
#pragma unroll
                for (int j = 0; j < 4; ++j)
                    mma8(acc[i][j], af[i], bf[j]);
        }
    }

#pragma unroll
    for (int i = 0; i < 4; ++i) {
        int r0 = m0 + mw + i * 16 + quad;
#pragma unroll
        for (int j = 0; j < 4; ++j) {
            int co = co0 + nw + j * 8 + tq * 2;
            float b0 = out_b[co], b1 = out_b[co + 1];
            float* base = g_ctxT + (size_t)sb * C_DIM * NTOK;
            base[(size_t)co * NTOK + r0]           = acc[i][j][0] + b0;
            base[(size_t)(co + 1) * NTOK + r0]     = acc[i][j][1] + b1;
            base[(size_t)co * NTOK + r0 + 8]       = acc[i][j][2] + b0;
            base[(size_t)(co + 1) * NTOK + r0 + 8] = acc[i][j][3] + b1;
        }
    }
}

// ---------------- K4: fused asym + proj + LN + ReLU (R11 structure) ----------------
// BM=128, BN=256, BK=16, 512 thr. A: register path, 2-stage smem, 1 sync/iter.
// B: 3-stage cp.async from g_projwT.
__global__ void __launch_bounds__(512) fused_proj_ln(const float* __restrict__ proj_b,
                                                     const float* __restrict__ ln_g,
                                                     const float* __restrict__ ln_b,
                                                     float* __restrict__ out) {
    extern __shared__ uint32_t sm[];
    uint32_t* As = sm;                       // 2 * 2176
    uint32_t* Bs = sm + 2 * 2176;            // 3 * 4224
    float2*  red = (float2*)(sm + 2 * 2176 + 3 * 4224);   // [128][4]

    const int m0 = blockIdx.y * 128;
    const int sb = blockIdx.z;
    const int side = sb >> 3, b = sb & 7;
    const float* featRB = g_featR + (size_t)b * (C_DIM * 4096);
    const float* ctxTB  = g_ctxT + (size_t)sb * C_DIM * NTOK;

    const int t = threadIdx.x;
    const int w = t >> 5, lane = t & 31, quad = lane >> 2, tq = lane & 3;
    const int wm = w & 3, nwi = w >> 2;
    const int mw = wm * 32, nwcol = nwi * 64;

    const int amm = t & 127, akb = t >> 7;   // fills k = akb + 4*i, i<4
    const int lm = m0 + amm;
    const int ly = lm >> 5, lx = lm & 31;
    const int qoff = ly * 64 + (side ? 32 + lx : lx);

    const uint32_t bbase0 = sptr(Bs);

    auto fillB = [&](int s, int kt) {
        const int j0 = kt * 16;
        const uint32_t bb = bbase0 + s * 16896;
#pragma unroll
        for (int i = 0; i < 2; ++i) {
            int idx = t + 512 * i;
            int k = idx >> 6, jg = idx & 63;
            CPA16(bb + (k * 264 + jg * 4) * 4, g_projwT + (j0 + k) * 256 + jg * 4);
        }
    };

    float acc[2][8][4];
#pragma unroll
    for (int i = 0; i < 2; ++i)
#pragma unroll
        for (int j = 0; j < 8; ++j)
#pragma unroll
            for (int p = 0; p < 4; ++p) acc[i][j][p] = 0.0f;

    fillB(0, 0); CPC();
    fillB(1, 1); CPC();

    float rq[4], rc[4];
#pragma unroll
    for (int i = 0; i < 4; ++i) {
        rq[i] = featRB[(size_t)(akb + 4 * i) * 4096 + qoff];
        As[(akb + 4 * i) * 136 + amm] = __float_as_uint(rq[i]);   // already rounded
        rc[i] = 0.0f;
    }

    for (int kt = 0; kt < 64; ++kt) {
        CPW1();
        __syncthreads();
        if (kt + 2 < 64) fillB((kt + 2) % 3, kt + 2);
        CPC();

        int np = (kt + 1) >> 4;
        if (kt < 63) {
#pragma unroll
            for (int i = 0; i < 4; ++i) {
                int jc = ((kt + 1) * 16 + akb + 4 * i) & 255;
                if (np != 1) rq[i] = featRB[(size_t)jc * 4096 + qoff];
                if (np != 0) rc[i] = ctxTB[(size_t)jc * NTOK + lm];
            }
        }

        const uint32_t* A = As + (kt & 1) * 2176;
        const uint32_t* B = Bs + (kt % 3) * 4224;
#pragma unroll
        for (int kb = 0; kb < 2; ++kb) {
            const int k0 = kb * 8;
            uint32_t af[2][4], bf[8][2];
#pragma unroll
            for (int i = 0; i < 2; ++i) {
                af[i][0] = A[(k0 + tq) * 136 + mw + i * 16 + quad];
                af[i][1] = A[(k0 + tq) * 136 + mw + i * 16 + quad + 8];
                af[i][2] = A[(k0 + tq + 4) * 136 + mw + i * 16 + quad];
                af[i][3] = A[(k0 + tq + 4) * 136 + mw + i * 16 + quad + 8];
            }
#pragma unroll
            for (int j = 0; j < 8; ++j) {
                bf[j][0] = B[(k0 + tq) * 264 + nwcol + j * 8 + quad];
                bf[j][1] = B[(k0 + tq + 4) * 264 + nwcol + j * 8 + quad];
            }
#pragma unroll
            for (int i = 0; i < 2; ++i)
#pragma unroll
                for (int j = 0; j < 8; ++j)
                    mma8(acc[i][j], af[i], bf[j]);
        }

        if (kt < 63) {
            uint32_t* An = As + ((kt + 1) & 1) * 2176;
#pragma unroll
            for (int i = 0; i < 4; ++i) {
                float v;
                if (np == 0)      v = rq[i];
                else if (np == 1) v = rc[i];
                else if (np == 2) v = fabsf(rq[i] - rc[i]);
                else              v = rq[i] * rc[i];
                An[(akb + 4 * i) * 136 + amm] = f2tf(v);
            }
        }
    }

    // ---- epilogue: +bias, LN(256), relu, transposed scatter ----
#pragma unroll
    for (int j = 0; j < 8; ++j) {
        int co = nwcol + j * 8 + tq * 2;
        float2 pb = *(const float2*)&proj_b[co];
#pragma unroll
        for (int i = 0; i < 2; ++i) {
            acc[i][j][0] += pb.x; acc[i][j][1] += pb.y;
            acc[i][j][2] += pb.x; acc[i][j][3] += pb.y;
        }
    }

    __syncthreads();
#pragma unroll
    for (int i = 0; i < 2; ++i)
#pragma unroll
        for (int u = 0; u < 2; ++u) {
            float s1 = 0.0f, s2 = 0.0f;
#pragma unroll
            for (int j = 0; j < 8; ++j) {
                float x0 = acc[i][j][2 * u], x1 = acc[i][j][2 * u + 1];
                s1 += x0 + x1; s2 += x0 * x0 + x1 * x1;
            }
            s1 += __shfl_xor_sync(0xffffffffu, s1, 1);
            s2 += __shfl_xor_sync(0xffffffffu, s2, 1);
            s1 += __shfl_xor_sync(0xffffffffu, s1, 2);
            s2 += __shfl_xor_sync(0xffffffffu, s2, 2);
            if (tq == 0) {
                int r = mw + i * 16 + u * 8 + quad;
                red[r * 4 + nwi] = make_float2(s1, s2);
            }
        }
    __syncthreads();

#pragma unroll
    for (int i = 0; i < 2; ++i)
#pragma unroll
        for (int u = 0; u < 2; ++u) {
            int r = mw + i * 16 + u * 8 + quad;
            float s1 = 0.0f, s2 = 0.0f;
#pragma unroll
            for (int p = 0; p < 4; ++p) { float2 v = red[r * 4 + p]; s1 += v.x; s2 += v.y; }
            float mu   = s1 * (1.0f / 256.0f);
            float var  = s2 * (1.0f / 256.0f) - mu * mu;
            float rstd = rsqrtf(var + 1e-5f);

            int grow = m0 + r;
            int y = grow >> 5, x = grow & 31;
            int xg = side ? (32 + x) : x;
            size_t obase = (size_t)b * C_DIM * 4096 + y * 64 + xg;
#pragma unroll
            for (int j = 0; j < 8; ++j) {
                int co = nwcol + j * 8 + tq * 2;
                float g0 = ln_g[co], g1 = ln_g[co + 1];
                float l0 = ln_b[co], l1 = ln_b[co + 1];
                float v0 = fmaxf((acc[i][j][2 * u]     - mu) * rstd * g0 + l0, 0.0f);
                float v1 = fmaxf((acc[i][j][2 * u + 1] - mu) * rstd * g1 + l1, 0.0f);
                out[obase + (size_t)co * 4096]       = v0;
                out[obase + (size_t)(co + 1) * 4096] = v1;
            }
        }
}

// ---------------- launch ----------------
extern "C" void kernel_launch(void* const* d_in, const int* in_sizes, int n_in,
                              void* d_out, int out_size) {
    const float* feat   = (const float*)d_in[0];
    const float* in_w   = (const float*)d_in[1];
    const float* in_b   = (const float*)d_in[2];
    const float* out_w  = (const float*)d_in[3];
    const float* out_b  = (const float*)d_in[4];
    const float* proj_w = (const float*)d_in[5];
    const float* proj_b = (const float*)d_in[6];
    const float* ln_g   = (const float*)d_in[7];
    const float* ln_b   = (const float*)d_in[8];
    float* out = (float*)d_out;

    const int QKV_SMEM = 3 * 2176 * 2 * 4;                         // 52224 B
    const int K4_SMEM  = (2 * 2176 + 3 * 4224) * 4 + 128 * 4 * 8;  // 72192 B
    cudaFuncSetAttribute(qkv_gemm,      cudaFuncAttributeMaxDynamicSharedMemorySize, QKV_SMEM);
    cudaFuncSetAttribute(outproj_gemm,  cudaFuncAttributeMaxDynamicSharedMemorySize, QKV_SMEM);
    cudaFuncSetAttribute(fused_proj_ln, cudaFuncAttributeMaxDynamicSharedMemorySize, K4_SMEM);

    prep_inputs<<<9216, 256>>>(feat, in_w, out_w, proj_w);
    qkv_gemm<<<dim3(6, 16, 16), 256, QKV_SMEM>>>(in_b);
    attn_kernel<<<dim3(16, 4, 16), 128>>>();
    outproj_gemm<<<dim3(2, 16, 16), 256, QKV_SMEM>>>(out_b);
    fused_proj_ln<<<dim3(1, 16, 16), 512, K4_SMEM>>>(proj_b, ln_g, ln_b, out);
}

// round 17
// speedup vs baseline: 1.4808x; 1.0124x over previous
#include <cuda_runtime.h>
#include <cstdint>
#include <math.h>

#define C_DIM 256
#define NTOK 2048          // 64 * 32 tokens per side per batch
#define SB_COUNT 16        // side(2) * batch(8)

// ---------------- scratch (static device globals; no allocation) ----------------
__device__ float g_featR[8 * C_DIM * 4096];             // tf32-rounded feat (same layout)
__device__ float g_qT[SB_COUNT * C_DIM * NTOK];         // q transposed [sb][c][n]
__device__ float g_kT[SB_COUNT * C_DIM * NTOK];
__device__ float g_vT[SB_COUNT * C_DIM * NTOK];
__device__ float g_attT[SB_COUNT * C_DIM * NTOK];       // attention ctx, transposed + tf32-rounded
__device__ float g_ctxT[SB_COUNT * C_DIM * NTOK];       // out-proj result, transposed [sb][c][n]
__device__ float g_inwT[C_DIM * 768];                   // in_w^T  (tf32-rounded)
__device__ float g_outwT[C_DIM * C_DIM];                // out_w^T (tf32-rounded)
__device__ float g_projwT[1024 * C_DIM];                // proj_w^T(tf32-rounded)

// ---------------- helpers ----------------
__device__ __forceinline__ uint32_t f2tf(float x) {
    uint32_t u; asm("cvt.rna.tf32.f32 %0, %1;" : "=r"(u) : "f"(x)); return u;
}
__device__ __forceinline__ void mma8(float* c, const uint32_t* a, const uint32_t* b) {
    asm volatile("mma.sync.aligned.m16n8k8.row.col.f32.tf32.tf32.f32 "
        "{%0,%1,%2,%3}, {%4,%5,%6,%7}, {%8,%9}, {%0,%1,%2,%3};"
        : "+f"(c[0]), "+f"(c[1]), "+f"(c[2]), "+f"(c[3])
        : "r"(a[0]), "r"(a[1]), "r"(a[2]), "r"(a[3]), "r"(b[0]), "r"(b[1]));
}
__device__ __forceinline__ uint32_t sptr(const void* p) {
    return (uint32_t)__cvta_generic_to_shared(p);
}
#define CPA4(d, s)  asm volatile("cp.async.ca.shared.global [%0], [%1], 4;"  :: "r"(d), "l"(s))
#define CPA16(d, s) asm volatile("cp.async.cg.shared.global [%0], [%1], 16;" :: "r"(d), "l"(s))
#define CPC()  asm volatile("cp.async.commit_group;")
#define CPW1() asm volatile("cp.async.wait_group 1;")
#define CPW0() asm volatile("cp.async.wait_group 0;")

// ---------------- K0: weight transpose + feat rounding (merged) ----------------
__global__ void prep_inputs(const float* __restrict__ feat,
                            const float* __restrict__ in_w,
                            const float* __restrict__ out_w,
                            const float* __restrict__ proj_w) {
    const int bid = blockIdx.x;
    if (bid < 1024) {
        int i = bid * 256 + threadIdx.x;
        if (i < 768 * 256) { int co = i >> 8;  int c = i & 255;  g_inwT[c * 768 + co]  = __uint_as_float(f2tf(in_w[i])); }
        if (i < 256 * 256) { int co = i >> 8;  int c = i & 255;  g_outwT[c * 256 + co] = __uint_as_float(f2tf(out_w[i])); }
        if (i < 256 * 1024){ int co = i >> 10; int j = i & 1023; g_projwT[j * 256 + co] = __uint_as_float(f2tf(proj_w[i])); }
    } else {
        int i = (bid - 1024) * 256 + threadIdx.x;   // float4 index
        float4 v = ((const float4*)feat)[i];
        v.x = __uint_as_float(f2tf(v.x)); v.y = __uint_as_float(f2tf(v.y));
        v.z = __uint_as_float(f2tf(v.z)); v.w = __uint_as_float(f2tf(v.w));
        ((float4*)g_featR)[i] = v;
    }
}

// ---------------- K1: QKV GEMM (tf32 mma, 3-stage cp.async) ----------------
// BM=128 BN=128 BK=16, 256 thr, warp tile 64x32. Writes q/k/v TRANSPOSED [sb][c][n].
__global__ void __launch_bounds__(256) qkv_gemm(const float* __restrict__ in_b) {
    extern __shared__ uint32_t sm[];
    uint32_t* As = sm;              // 3 stages * 2176 words
    uint32_t* Bs = sm + 3 * 2176;

    const int co0 = blockIdx.x * 128;
    const int m0  = blockIdx.y * 128;
    const int sb  = blockIdx.z;
    const int side = sb >> 3, b = sb & 7;
    const bool is_q = (co0 < 256);
    const float* featRB = g_featR + (size_t)b * (C_DIM * 4096);

    const int t = threadIdx.x;
    const int w = t >> 5, lane = t & 31, quad = lane >> 2, tq = lane & 3;
    const int mw = (w & 1) * 64, nw = (w >> 1) * 32;

    const int mm = t & 127;
    const int m  = m0 + mm;
    const int yq = m >> 5, xq = m & 31;
    const int colg = is_q ? (side ? 32 + xq : xq) : (side ? 31 - xq : 63 - xq);
    const int aoff = yq * 64 + colg;
    const int kb0 = t >> 7;   // fills k = kb0 + 2*i

    const uint32_t abase0 = sptr(As), bbase0 = sptr(Bs);

    auto fill = [&](int s, int kt) {
        const int c0 = kt * 16;
        const uint32_t ab = abase0 + s * 8704;
        const uint32_t bb = bbase0 + s * 8704;
#pragma unroll
        for (int i = 0; i < 8; ++i) {
            int k = kb0 + 2 * i;
            CPA4(ab + (k * 136 + mm) * 4, featRB + (size_t)(c0 + k) * 4096 + aoff);
        }
#pragma unroll
        for (int i = 0; i < 2; ++i) {
            int idx = t + 256 * i;
            int k = idx >> 5, jg = idx & 31;
            CPA16(bb + (k * 136 + jg * 4) * 4, g_inwT + (c0 + k) * 768 + co0 + jg * 4);
        }
    };

    float acc[4][4][4];
#pragma unroll
    for (int i = 0; i < 4; ++i)
#pragma unroll
        for (int j = 0; j < 4; ++j)
#pragma unroll
            for (int p = 0; p < 4; ++p) acc[i][j][p] = 0.0f;

    fill(0, 0); CPC();
    fill(1, 1); CPC();

    for (int kt = 0; kt < 16; ++kt) {
        CPW1();
        __syncthreads();
        if (kt + 2 < 16) fill((kt + 2) % 3, kt + 2);
        CPC();
        const uint32_t* A = As + (kt % 3) * 2176;
        const uint32_t* B = Bs + (kt % 3) * 2176;
#pragma unroll
        for (int kb = 0; kb < 2; ++kb) {
            const int k0 = kb * 8;
            uint32_t af[4][4], bf[4][2];
#pragma unroll
            for (int i = 0; i < 4; ++i) {
                af[i][0] = A[(k0 + tq) * 136 + mw + i * 16 + quad];
                af[i][1] = A[(k0 + tq) * 136 + mw + i * 16 + quad + 8];
                af[i][2] = A[(k0 + tq + 4) * 136 + mw + i * 16 + quad];
                af[i][3] = A[(k0 + tq + 4) * 136 + mw + i * 16 + quad + 8];
            }
#pragma unroll
            for (int j = 0; j < 4; ++j) {
                bf[j][0] = B[(k0 + tq) * 136 + nw + j * 8 + quad];
                bf[j][1] = B[(k0 + tq + 4) * 136 + nw + j * 8 + quad];
            }
#pragma unroll
            for (int i = 0; i < 4; ++i)
#pragma unroll
                for (int j = 0; j < 4; ++j)
                    mma8(acc[i][j], af[i], bf[j]);
        }
    }

    // transposed epilogue: dst[cl][row]
#pragma unroll
    for (int i = 0; i < 4; ++i) {
        int r0 = m0 + mw + i * 16 + quad;
#pragma unroll
        for (int j = 0; j < 4; ++j) {
            int co = co0 + nw + j * 8 + tq * 2;
            float b0 = in_b[co], b1 = in_b[co + 1];
            float* dst = (co < 256) ? g_qT : ((co < 512) ? g_kT : g_vT);
            int cl = co & 255;
            float* base0 = dst + ((size_t)sb * C_DIM + cl) * NTOK;
            float* base1 = base0 + NTOK;
            base0[r0]     = acc[i][j][0] + b0;
            base1[r0]     = acc[i][j][1] + b1;
            base0[r0 + 8] = acc[i][j][2] + b0;
            base1[r0 + 8] = acc[i][j][3] + b1;
        }
    }
}

// ---------------- K2: sparse attention v2 (thread-per-token, smem tiles) ----------------
__global__ void __launch_bounds__(128, 4) attn_kernel() {
    __shared__ float smk[2][16 * 264];

    const int t = threadIdx.x;
    const int yblk = blockIdx.x;     // 0..15 (4 rows each)
    const int hd   = blockIdx.y;     // 0..3
    const int sb   = blockIdx.z;     // 0..15
    const int n0 = yblk * 128;
    const int n  = n0 + t;
    const int y = n >> 5, x = n & 31;
    const int lt = 64 + t;           // local token index within tile (tile starts at n0-64)

    const float* qTB = g_qT + ((size_t)sb * C_DIM + hd * 64) * NTOK;
    const float* kTB = g_kT + ((size_t)sb * C_DIM + hd * 64) * NTOK;
    const float* vTB = g_vT + ((size_t)sb * C_DIM + hd * 64) * NTOK;

    // zero pad columns (cols [0,4) and [260,264) of each of 16 rows, both buffers)
    for (int i = t; i < 256; i += 128) {
        int buf = i >> 7, rem = i & 127;
        int row = rem >> 3, c8 = rem & 7;
        int col = (c8 < 4) ? c8 : (256 + c8);
        smk[buf][row * 264 + col] = 0.0f;
    }

    const int ody[13] = {0, 0, 0, 0, 0, -1, -1, -1, 1, 1, 1, -2, 2};
    const int odx[13] = {0,-1, 1,-2, 2,  0, -1,  1, 0,-1, 1,  0, 0};

    bool va[13];
#pragma unroll
    for (int i = 0; i < 13; ++i) {
        int yy = y + ody[i], xx = x + odx[i];
        va[i] = (yy >= 0) && (yy < 64) && (xx >= 0) && (xx < 32);
    }

    // q in registers (reused 13x per channel; later reused as output accumulator)
    float qa[64];
#pragma unroll
    for (int d = 0; d < 64; ++d) qa[d] = qTB[(size_t)d * NTOK + n];

    const int y0m2 = (n0 >> 5) - 2;
    auto fill = [&](int buf, int c) {
        const float* src = (c < 4) ? (kTB + (size_t)(c * 16) * NTOK)
                                   : (vTB + (size_t)((c - 4) * 16) * NTOK);
        uint32_t dst = sptr(&smk[buf][0]);
#pragma unroll
        for (int i = 0; i < 8; ++i) {
            int idx = t + 128 * i;
            int d = idx >> 6, jj = idx & 63;
            int yy = y0m2 + (jj >> 3);
            int yc = min(max(yy, 0), 63);
            int sn = yc * 32 + (jj & 7) * 4;
            CPA16(dst + (d * 264 + 4 + jj * 4) * 4, src + (size_t)d * NTOK + sn);
        }
    };

    float sc[13];
#pragma unroll
    for (int i = 0; i < 13; ++i) sc[i] = 0.0f;

    fill(0, 0); CPC();

#pragma unroll
    for (int c = 0; c < 8; ++c) {
        if (c < 7) { fill((c + 1) & 1, c + 1); CPC(); CPW1(); }
        else       { CPW0(); }
        __syncthreads();
        const float* buf = smk[c & 1];
        if (c < 4) {
#pragma unroll
            for (int dd = 0; dd < 16; ++dd) {
                float qv = qa[c * 16 + dd];
                const float* base = buf + dd * 264 + 4 + lt;
#pragma unroll
                for (int i = 0; i < 13; ++i)
                    sc[i] += qv * base[ody[i] * 32 + odx[i]];
            }
            if (c == 3) {
                float mx = -1e30f;
#pragma unroll
                for (int i = 0; i < 13; ++i) {
                    sc[i] = va[i] ? sc[i] * 0.125f : -1e30f;
                    mx = fmaxf(mx, sc[i]);
                }
                float ssum = 0.0f;
#pragma unroll
                for (int i = 0; i < 13; ++i) {
                    sc[i] = va[i] ? __expf(sc[i] - mx) : 0.0f;
                    ssum += sc[i];
                }
                float inv = 1.0f / ssum;
#pragma unroll
                for (int i = 0; i < 13; ++i) sc[i] *= inv;
            }
        } else {
#pragma unroll
            for (int dd = 0; dd < 16; ++dd) {
                const float* base = buf + dd * 264 + 4 + lt;
                float a = 0.0f;
#pragma unroll
                for (int i = 0; i < 13; ++i)
                    a += sc[i] * base[ody[i] * 32 + odx[i]];
                qa[(c - 4) * 16 + dd] = a;
            }
        }
        __syncthreads();
    }

    // store transposed + tf32-rounded, coalesced over n
    float* oB = g_attT + ((size_t)sb * C_DIM + hd * 64) * NTOK + n;
#pragma unroll
    for (int d = 0; d < 64; ++d)
        oB[(size_t)d * NTOK] = __uint_as_float(f2tf(qa[d]));
}

// ---------------- K3: out-proj GEMM (tf32 mma, 3-stage cp.async), writes g_ctxT ----------------
__global__ void __launch_bounds__(256) outproj_gemm(const float* __restrict__ out_b) {
    extern __shared__ uint32_t sm[];
    uint32_t* As = sm;
    uint32_t* Bs = sm + 3 * 2176;

    const int co0 = blockIdx.x * 128;
    const int m0  = blockIdx.y * 128;
    const int sb  = blockIdx.z;
    const float* attTB = g_attT + (size_t)sb * C_DIM * NTOK;

    const int t = threadIdx.x;
    const int w = t >> 5, lane = t & 31, quad = lane >> 2, tq = lane & 3;
    const int mw = (w & 1) * 64, nw = (w >> 1) * 32;

    const uint32_t abase0 = sptr(As), bbase0 = sptr(Bs);

    auto fill = [&](int s, int kt) {
        const int c0 = kt * 16;
        const uint32_t ab = abase0 + s * 8704;
        const uint32_t bb = bbase0 + s * 8704;
#pragma unroll
        for (int i = 0; i < 2; ++i) {
            int idx = t + 256 * i;
            int k = idx >> 5, mg = idx & 31;
            CPA16(ab + (k * 136 + mg * 4) * 4, attTB + (size_t)(c0 + k) * NTOK + m0 + mg * 4);
            CPA16(bb + (k * 136 + mg * 4) * 4, g_outwT + (c0 + k) * 256 + co0 + mg * 4);
        }
    };

    float acc[4][4][4];
#pragma unroll
    for (int i = 0; i < 4; ++i)
#pragma unroll
        for (int j = 0; j < 4; ++j)
#pragma unroll
            for (int p = 0; p < 4; ++p) acc[i][j][p] = 0.0f;

    fill(0, 0); CPC();
    fill(1, 1); CPC();

    for (int kt = 0; kt < 16; ++kt) {
        CPW1();
        __syncthreads();
        if (kt + 2 < 16) fill((kt + 2) % 3, kt + 2);
        CPC();
        const uint32_t* A = As + (kt % 3) * 2176;
        const uint32_t* B = Bs + (kt % 3) * 2176;
#pragma unroll
        for (int kb = 0; kb < 2; ++kb) {
            const int k0 = kb * 8;
            uint32_t af[4][4], bf[4][2];
#pragma unroll
            for (int i = 0; i < 4; ++i) {
                af[i][0] = A[(k0 + tq) * 136 + mw + i * 16 + quad];
                af[i][1] = A[(k0 + tq) * 136 + mw + i * 16 + quad + 8];
                af[i][2] = A[(k0 + tq + 4) * 136 + mw + i * 16 + quad];
                af[i][3] = A[(k0 + tq + 4) * 136 + mw + i * 16 + quad + 8];
            }
#pragma unroll
            for (int j = 0; j < 4; ++j) {
                bf[j][0] = B[(k0 + tq) * 136 + nw + j * 8 + quad];
                bf[j][1] = B[(k0 + tq + 4) * 136 + nw + j * 8 + quad];
            }
#pragma unroll
            for (int i = 0; i < 4; ++i)
#pragma unroll
                for (int j = 0; j < 4; ++j)
                    mma8(acc[i][j], af[i], bf[j]);
        }
    }

#pragma unroll
    for (int i = 0; i < 4; ++i) {
        int r0 = m0 + mw + i * 16 + quad;
#pragma unroll
        for (int j = 0; j < 4; ++j) {
            int co = co0 + nw + j * 8 + tq * 2;
            float b0 = out_b[co], b1 = out_b[co + 1];
            float* base = g_ctxT + (size_t)sb * C_DIM * NTOK;
            base[(size_t)co * NTOK + r0]           = acc[i][j][0] + b0;
            base[(size_t)(co + 1) * NTOK + r0]     = acc[i][j][1] + b1;
            base[(size_t)co * NTOK + r0 + 8]       = acc[i][j][2] + b0;
            base[(size_t)(co + 1) * NTOK + r0 + 8] = acc[i][j][3] + b1;
        }
    }
}

// ---------------- K4: fused asym + proj + LN + ReLU ----------------
// BM=64, BN=256, BK=16, 256 thr (2 CTA/SM), warp tile 32x64 (2 m-warps x 4 n-warps).
// A: register path, 2-stage smem (16x72 words/stage). B: 3-stage cp.async.
__global__ void __launch_bounds__(256, 2) fused_proj_ln(const float* __restrict__ proj_b,
                                                        const float* __restrict__ ln_g,
                                                        const float* __restrict__ ln_b,
                                                        float* __restrict__ out) {
    extern __shared__ uint32_t sm[];
    uint32_t* As = sm;                       // 2 * 1152 (stage = 16 k * 72)
    uint32_t* Bs = sm + 2 * 1152;            // 3 * 4224
    float2*  red = (float2*)(sm + 2 * 1152 + 3 * 4224);   // [64][4]

    const int m0 = blockIdx.y * 64;
    const int sb = blockIdx.z;
    const int side = sb >> 3, b = sb & 7;
    const float* featRB = g_featR + (size_t)b * (C_DIM * 4096);
    const float* ctxTB  = g_ctxT + (size_t)sb * C_DIM * NTOK;

    const int t = threadIdx.x;
    const int w = t >> 5, lane = t & 31, quad = lane >> 2, tq = lane & 3;
    const int wm = w & 1, nwi = w >> 1;      // 2 m-warps, 4 n-warps
    const int mw = wm * 32, nwcol = nwi * 64;

    const int amm = t & 63, akb = t >> 6;    // fills k = akb + 4*i, i<4
    const int lm = m0 + amm;
    const int ly = lm >> 5, lx = lm & 31;
    const int qoff = ly * 64 + (side ? 32 + lx : lx);

    const uint32_t bbase0 = sptr(Bs);

    auto fillB = [&](int s, int kt) {
        const int j0 = kt * 16;
        const uint32_t bb = bbase0 + s * 16896;
#pragma unroll
        for (int i = 0; i < 4; ++i) {
            int idx = t + 256 * i;
            int k = idx >> 6, jg = idx & 63;
            CPA16(bb + (k * 264 + jg * 4) * 4, g_projwT + (j0 + k) * 256 + jg * 4);
        }
    };

    float acc[2][8][4];
#pragma unroll
    for (int i = 0; i < 2; ++i)
#pragma unroll
        for (int j = 0; j < 8; ++j)
#pragma unroll
            for (int p = 0; p < 4; ++p) acc[i][j][p] = 0.0f;

    fillB(0, 0); CPC();
    fillB(1, 1); CPC();

    float rq[4], rc[4];
#pragma unroll
    for (int i = 0; i < 4; ++i) {
        rq[i] = featRB[(size_t)(akb + 4 * i) * 4096 + qoff];
        As[(akb + 4 * i) * 72 + amm] = __float_as_uint(rq[i]);   // already rounded
        rc[i] = 0.0f;
    }

    for (int kt = 0; kt < 64; ++kt) {
        CPW1();
        __syncthreads();
        if (kt + 2 < 64) fillB((kt + 2) % 3, kt + 2);
        CPC();

        int np = (kt + 1) >> 4;
        if (kt < 63) {
#pragma unroll
            for (int i = 0; i < 4; ++i) {
                int jc = ((kt + 1) * 16 + akb + 4 * i) & 255;
                if (np != 1) rq[i] = featRB[(size_t)jc * 4096 + qoff];
                if (np != 0) rc[i] = ctxTB[(size_t)jc * NTOK + lm];
            }
        }

        const uint32_t* A = As + (kt & 1) * 1152;
        const uint32_t* B = Bs + (kt % 3) * 4224;
#pragma unroll
        for (int kb = 0; kb < 2; ++kb) {
            const int k0 = kb * 8;
            uint32_t af[2][4], bf[8][2];
#pragma unroll
            for (int i = 0; i < 2; ++i) {
                af[i][0] = A[(k0 + tq) * 72 + mw + i * 16 + quad];
                af[i][1] = A[(k0 + tq) * 72 + mw + i * 16 + quad + 8];
                af[i][2] = A[(k0 + tq + 4) * 72 + mw + i * 16 + quad];
                af[i][3] = A[(k0 + tq + 4) * 72 + mw + i * 16 + quad + 8];
            }
#pragma unroll
            for (int j = 0; j < 8; ++j) {
                bf[j][0] = B[(k0 + tq) * 264 + nwcol + j * 8 + quad];
                bf[j][1] = B[(k0 + tq + 4) * 264 + nwcol + j * 8 + quad];
            }
#pragma unroll
            for (int i = 0; i < 2; ++i)
#pragma unroll
                for (int j = 0; j < 8; ++j)
                    mma8(acc[i][j], af[i], bf[j]);
        }

        if (kt < 63) {
            const int np2 = np;
            uint32_t* An = As + ((kt + 1) & 1) * 1152;
#pragma unroll
            for (int i = 0; i < 4; ++i) {
                float v;
                if (np2 == 0)      v = rq[i];
                else if (np2 == 1) v = rc[i];
                else if (np2 == 2) v = fabsf(rq[i] - rc[i]);
                else               v = rq[i] * rc[i];
                An[(akb + 4 * i) * 72 + amm] = f2tf(v);
            }
        }
    }

    // ---- epilogue: +bias, LN(256), relu, transposed scatter ----
#pragma unroll
    for (int j = 0; j < 8; ++j) {
        int co = nwcol + j * 8 + tq * 2;
        float2 pb = *(const float2*)&proj_b[co];
#pragma unroll
        for (int i = 0; i < 2; ++i) {
            acc[i][j][0] += pb.x; acc[i][j][1] += pb.y;
            acc[i][j][2] += pb.x; acc[i][j][3] += pb.y;
        }
    }

    __syncthreads();
#pragma unroll
    for (int i = 0; i < 2; ++i)
#pragma unroll
        for (int u = 0; u < 2; ++u) {
            float s1 = 0.0f, s2 = 0.0f;
#pragma unroll
            for (int j = 0; j < 8; ++j) {
                float x0 = acc[i][j][2 * u], x1 = acc[i][j][2 * u + 1];
                s1 += x0 + x1; s2 += x0 * x0 + x1 * x1;
            }
            s1 += __shfl_xor_sync(0xffffffffu, s1, 1);
            s2 += __shfl_xor_sync(0xffffffffu, s2, 1);
            s1 += __shfl_xor_sync(0xffffffffu, s1, 2);
            s2 += __shfl_xor_sync(0xffffffffu, s2, 2);
            if (tq == 0) {
                int r = mw + i * 16 + u * 8 + quad;
                red[r * 4 + nwi] = make_float2(s1, s2);
            }
        }
    __syncthreads();

#pragma unroll
    for (int i = 0; i < 2; ++i)
#pragma unroll
        for (int u = 0; u < 2; ++u) {
            int r = mw + i * 16 + u * 8 + quad;
            float s1 = 0.0f, s2 = 0.0f;
#pragma unroll
            for (int p = 0; p < 4; ++p) { float2 v = red[r * 4 + p]; s1 += v.x; s2 += v.y; }
            float mu   = s1 * (1.0f / 256.0f);
            float var  = s2 * (1.0f / 256.0f) - mu * mu;
            float rstd = rsqrtf(var + 1e-5f);

            int grow = m0 + r;
            int y = grow >> 5, x = grow & 31;
            int xg = side ? (32 + x) : x;
            size_t obase = (size_t)b * C_DIM * 4096 + y * 64 + xg;
#pragma unroll
            for (int j = 0; j < 8; ++j) {
                int co = nwcol + j * 8 + tq * 2;
                float g0 = ln_g[co], g1 = ln_g[co + 1];
                float l0 = ln_b[co], l1 = ln_b[co + 1];
                float v0 = fmaxf((acc[i][j][2 * u]     - mu) * rstd * g0 + l0, 0.0f);
                float v1 = fmaxf((acc[i][j][2 * u + 1] - mu) * rstd * g1 + l1, 0.0f);
                out[obase + (size_t)co * 4096]       = v0;
                out[obase + (size_t)(co + 1) * 4096] = v1;
            }
        }
}

// ---------------- launch ----------------
extern "C" void kernel_launch(void* const* d_in, const int* in_sizes, int n_in,
                              void* d_out, int out_size) {
    const float* feat   = (const float*)d_in[0];
    const float* in_w   = (const float*)d_in[1];
    const float* in_b   = (const float*)d_in[2];
    const float* out_w  = (const float*)d_in[3];
    const float* out_b  = (const float*)d_in[4];
    const float* proj_w = (const float*)d_in[5];
    const float* proj_b = (const float*)d_in[6];
    const float* ln_g   = (const float*)d_in[7];
    const float* ln_b   = (const float*)d_in[8];
    float* out = (float*)d_out;

    const int QKV_SMEM = 3 * 2176 * 2 * 4;                         // 52224 B
    const int K4_SMEM  = (2 * 1152 + 3 * 4224) * 4 + 64 * 4 * 8;   // 61952 B
    cudaFuncSetAttribute(qkv_gemm,      cudaFuncAttributeMaxDynamicSharedMemorySize, QKV_SMEM);
    cudaFuncSetAttribute(outproj_gemm,  cudaFuncAttributeMaxDynamicSharedMemorySize, QKV_SMEM);
    cudaFuncSetAttribute(fused_proj_ln, cudaFuncAttributeMaxDynamicSharedMemorySize, K4_SMEM);

    prep_inputs<<<9216, 256>>>(feat, in_w, out_w, proj_w);
    qkv_gemm<<<dim3(6, 16, 16), 256, QKV_SMEM>>>(in_b);
    attn_kernel<<<dim3(16, 4, 16), 128>>>();
    outproj_gemm<<<dim3(2, 16, 16), 256, QKV_SMEM>>>(out_b);
    fused_proj_ln<<<dim3(1, 32, 16), 256, K4_SMEM>>>(proj_b, ln_g, ln_b, out);
}